// round 6
// baseline (speedup 1.0000x reference)
#include <cuda_runtime.h>
#include <cstdint>

// Problem constants
constexpr int HID   = 1024;
constexpr int INTER = 4096;
constexpr int NE    = 8;
constexpr int NT    = 8192;

// Tiling
constexpr int BM = 128;
constexpr int BN = 128;
constexpr int BK = 16;
// Total routed pairs = TOP_K * NT = 16384 -> sum_e ceil(cnt_e/BM) <= 16384/128 + 8 = 136
constexpr int MAX_TILES = (2 * NT) / BM + NE;   // 136

// ---------------- device scratch (no allocations allowed) ----------------
__device__ int   g_tok[NE][NT];
__device__ float g_wt [NE][NT];
__device__ int   g_cnt[NE];
__device__ int   g_top1[NE];
__device__ float g_psum[NE];
__device__ int   g_tile_e[MAX_TILES];
__device__ int   g_tile_base[MAX_TILES];
__device__ float g_h[(long long)MAX_TILES * BM * INTER];   // ~285 MB fp32 scratch
// tf32-pre-rounded copies (rounding hoisted out of GEMM inner loops)
__device__ float g_xr [NT * HID];
__device__ float g_w1r[(long long)NE * HID * INTER];
__device__ float g_w2r[(long long)NE * INTER * HID];

// ---------------- helpers ----------------
__device__ __forceinline__ void cp_async16(void* smem_dst, const void* gmem_src){
    uint32_t d = (uint32_t)__cvta_generic_to_shared(smem_dst);
    asm volatile("cp.async.cg.shared.global [%0], [%1], 16;\n" :: "r"(d), "l"(gmem_src));
}
__device__ __forceinline__ void cp_commit(){ asm volatile("cp.async.commit_group;\n" ::: "memory"); }
__device__ __forceinline__ void cp_wait1(){ asm volatile("cp.async.wait_group 1;\n" ::: "memory"); }

// f32 -> tf32 round-to-nearest (used only in prep / epilogue, NOT in mainloops)
__device__ __forceinline__ uint32_t to_tf32(float f){
    uint32_t r;
    asm volatile("cvt.rna.tf32.f32 %0, %1;\n" : "=r"(r) : "f"(f));
    return r;
}
__device__ __forceinline__ float round_tf32(float f){
    return __uint_as_float(to_tf32(f));
}

__device__ __forceinline__ void mma8(float4& d,
                                     uint32_t a0, uint32_t a1, uint32_t a2, uint32_t a3,
                                     uint32_t b0, uint32_t b1){
    asm volatile("mma.sync.aligned.m16n8k8.row.col.f32.tf32.tf32.f32 "
                 "{%0,%1,%2,%3}, {%4,%5,%6,%7}, {%8,%9}, {%0,%1,%2,%3};\n"
                 : "+f"(d.x), "+f"(d.y), "+f"(d.z), "+f"(d.w)
                 : "r"(a0), "r"(a1), "r"(a2), "r"(a3), "r"(b0), "r"(b1));
}

// ---------------- kernel 0: zero output + counters ----------------
__global__ void k_init(float* out, int n){
    int stride = gridDim.x * blockDim.x;
    for (int i = blockIdx.x * blockDim.x + threadIdx.x; i < n; i += stride) out[i] = 0.f;
    if (blockIdx.x == 0 && threadIdx.x < NE){
        g_cnt[threadIdx.x]  = 0;
        g_top1[threadIdx.x] = 0;
        g_psum[threadIdx.x] = 0.f;
    }
}

// ---------------- kernel 0b: pre-round x / W1 / W2 to tf32 ----------------
__global__ void k_prep(const float* __restrict__ x,
                       const float* __restrict__ w1,
                       const float* __restrict__ w2){
    long long stride = (long long)gridDim.x * blockDim.x;
    long long t0 = (long long)blockIdx.x * blockDim.x + threadIdx.x;

    const long long NX  = (long long)NT * HID / 4;
    const long long NW  = (long long)NE * HID * INTER / 4;

    const float4* xs = reinterpret_cast<const float4*>(x);
    float4* xd = reinterpret_cast<float4*>(g_xr);
    for (long long i = t0; i < NX; i += stride){
        float4 v = xs[i];
        v.x = round_tf32(v.x); v.y = round_tf32(v.y);
        v.z = round_tf32(v.z); v.w = round_tf32(v.w);
        xd[i] = v;
    }
    const float4* w1s = reinterpret_cast<const float4*>(w1);
    float4* w1d = reinterpret_cast<float4*>(g_w1r);
    for (long long i = t0; i < NW; i += stride){
        float4 v = w1s[i];
        v.x = round_tf32(v.x); v.y = round_tf32(v.y);
        v.z = round_tf32(v.z); v.w = round_tf32(v.w);
        w1d[i] = v;
    }
    const float4* w2s = reinterpret_cast<const float4*>(w2);
    float4* w2d = reinterpret_cast<float4*>(g_w2r);
    for (long long i = t0; i < NW; i += stride){
        float4 v = w2s[i];
        v.x = round_tf32(v.x); v.y = round_tf32(v.y);
        v.z = round_tf32(v.z); v.w = round_tf32(v.w);
        w2d[i] = v;
    }
}

// ---------------- kernel 1: router (1 warp per token) ----------------
__global__ void k_router(const float* __restrict__ x, const float* __restrict__ rw){
    int t = blockIdx.x * (blockDim.x >> 5) + (threadIdx.x >> 5);
    int lane = threadIdx.x & 31;
    if (t >= NT) return;
    const float4* xr = reinterpret_cast<const float4*>(x + (size_t)t * HID);
    float acc[NE];
#pragma unroll
    for (int e = 0; e < NE; e++) acc[e] = 0.f;
#pragma unroll
    for (int j = 0; j < 8; j++){
        float4 xv = xr[lane + 32 * j];
#pragma unroll
        for (int e = 0; e < NE; e++){
            float4 wv = reinterpret_cast<const float4*>(rw + e * HID)[lane + 32 * j];
            acc[e] += xv.x * wv.x + xv.y * wv.y + xv.z * wv.z + xv.w * wv.w;
        }
    }
#pragma unroll
    for (int o = 16; o > 0; o >>= 1)
#pragma unroll
        for (int e = 0; e < NE; e++)
            acc[e] += __shfl_xor_sync(0xffffffffu, acc[e], o);

    if (lane == 0){
        float m = acc[0];
#pragma unroll
        for (int e = 1; e < NE; e++) m = fmaxf(m, acc[e]);
        float p[NE]; float s = 0.f;
#pragma unroll
        for (int e = 0; e < NE; e++){ p[e] = expf(acc[e] - m); s += p[e]; }
        float inv = 1.f / s;
#pragma unroll
        for (int e = 0; e < NE; e++) p[e] *= inv;
        // top-2 (ties -> lower index, matching jax top_k)
        int i1 = 0;
#pragma unroll
        for (int e = 1; e < NE; e++) if (p[e] > p[i1]) i1 = e;
        int i2 = (i1 == 0) ? 1 : 0;
#pragma unroll
        for (int e = 0; e < NE; e++) if (e != i1 && p[e] > p[i2]) i2 = e;
        float w1 = p[i1], w2 = p[i2];
        float rs = 1.f / (w1 + w2);
        w1 *= rs; w2 *= rs;
        int pos1 = atomicAdd(&g_cnt[i1], 1);
        g_tok[i1][pos1] = t; g_wt[i1][pos1] = w1;
        int pos2 = atomicAdd(&g_cnt[i2], 1);
        g_tok[i2][pos2] = t; g_wt[i2][pos2] = w2;
        atomicAdd(&g_top1[i1], 1);
#pragma unroll
        for (int e = 0; e < NE; e++) atomicAdd(&g_psum[e], p[e]);
    }
}

// ---------------- kernel 2: tile map + aux loss ----------------
__global__ void k_setup(float* out, int out_size){
    if (threadIdx.x != 0 || blockIdx.x != 0) return;
    int nt = 0;
    for (int e = 0; e < NE; e++){
        int c = g_cnt[e];
        for (int b = 0; b < c; b += BM){
            g_tile_e[nt] = e; g_tile_base[nt] = b; nt++;
        }
    }
    for (; nt < MAX_TILES; nt++) g_tile_e[nt] = -1;

    float aux = 0.f;
    for (int e = 0; e < NE; e++)
        aux += ((float)g_top1[e] / (float)NT) * (g_psum[e] / (float)NT);
    aux *= (float)NE;
    if (out_size > NT * HID) out[NT * HID] = aux;
}

// ---------------- kernel 3: grouped GEMM1 (gather x @ W1, SiLU) ----------------
__global__ void __launch_bounds__(256, 2) k_gemm1(const float* __restrict__ w1_unused){
    int e = g_tile_e[blockIdx.y];
    if (e < 0) return;
    int base = g_tile_base[blockIdx.y];
    int cnt  = g_cnt[e];
    int n0   = blockIdx.x * BN;

    __shared__ __align__(16) float As[2][BM][BK + 4];  // pitch 20 -> conflict-free A frags
    __shared__ __align__(16) float Bs[2][BK][BN + 8];  // pitch 136 -> conflict-free B frags
    __shared__ int   s_tok[BM];

    int tid = threadIdx.x;
    if (tid < BM){
        int idx = base + tid;
        if (idx >= cnt) idx = cnt - 1;      // clamp pad rows (weight 0 later)
        s_tok[tid] = g_tok[e][idx];
    }
    __syncthreads();

    const float* wp = g_w1r + (size_t)e * HID * INTER;

    int arow = tid >> 2;                    // 0..63
    int af4  = (tid & 3) * 4;
    int brow = tid >> 5;                    // 0..7
    int bf4  = (tid & 31) * 4;

    const float* asrc0 = g_xr + (size_t)s_tok[arow]      * HID + af4;
    const float* asrc1 = g_xr + (size_t)s_tok[arow + 64] * HID + af4;

    float4 c[2][8];
#pragma unroll
    for (int mi = 0; mi < 2; mi++)
#pragma unroll
        for (int ni = 0; ni < 8; ni++) c[mi][ni] = make_float4(0.f, 0.f, 0.f, 0.f);

    int w    = tid >> 5;
    int lane = tid & 31;
    int wrow = (w & 3) * 32;
    int wcol = (w >> 2) * 64;
    int g    = lane >> 2;
    int q    = lane & 3;

    auto load_tile = [&](int buf, int k0){
        cp_async16(&As[buf][arow     ][af4], asrc0 + k0);
        cp_async16(&As[buf][arow + 64][af4], asrc1 + k0);
        cp_async16(&Bs[buf][brow     ][bf4], wp + (size_t)(k0 + brow    ) * INTER + n0 + bf4);
        cp_async16(&Bs[buf][brow + 8 ][bf4], wp + (size_t)(k0 + brow + 8) * INTER + n0 + bf4);
    };

    load_tile(0, 0);
    cp_commit();

    const int KT = HID / BK;   // 64
    for (int it = 0; it < KT; it++){
        int cur = it & 1;
        if (it + 1 < KT) load_tile(cur ^ 1, (it + 1) * BK);
        cp_commit();
        cp_wait1();
        __syncthreads();
#pragma unroll
        for (int kk = 0; kk < 2; kk++){
            int ko = kk * 8;
            uint32_t a[2][4];
#pragma unroll
            for (int mi = 0; mi < 2; mi++){
                int rb = wrow + mi * 16;
                a[mi][0] = __float_as_uint(As[cur][rb + g    ][ko + q    ]);
                a[mi][1] = __float_as_uint(As[cur][rb + g + 8][ko + q    ]);
                a[mi][2] = __float_as_uint(As[cur][rb + g    ][ko + q + 4]);
                a[mi][3] = __float_as_uint(As[cur][rb + g + 8][ko + q + 4]);
            }
#pragma unroll
            for (int ni = 0; ni < 8; ni++){
                int col = wcol + ni * 8 + g;
                uint32_t b0 = __float_as_uint(Bs[cur][ko + q    ][col]);
                uint32_t b1 = __float_as_uint(Bs[cur][ko + q + 4][col]);
#pragma unroll
                for (int mi = 0; mi < 2; mi++)
                    mma8(c[mi][ni], a[mi][0], a[mi][1], a[mi][2], a[mi][3], b0, b1);
            }
        }
        __syncthreads();
    }

    // epilogue: SiLU, round to tf32, store to h scratch
    long long hbase = (long long)blockIdx.y * BM;
#pragma unroll
    for (int mi = 0; mi < 2; mi++){
        int r0 = wrow + mi * 16 + g;
#pragma unroll
        for (int ni = 0; ni < 8; ni++){
            int col = n0 + wcol + ni * 8 + q * 2;
            float4 v = c[mi][ni];
            float2 u0, u1;
            u0.x = round_tf32(v.x / (1.f + __expf(-v.x)));
            u0.y = round_tf32(v.y / (1.f + __expf(-v.y)));
            u1.x = round_tf32(v.z / (1.f + __expf(-v.z)));
            u1.y = round_tf32(v.w / (1.f + __expf(-v.w)));
            *reinterpret_cast<float2*>(&g_h[(hbase + r0    ) * INTER + col]) = u0;
            *reinterpret_cast<float2*>(&g_h[(hbase + r0 + 8) * INTER + col]) = u1;
        }
    }
}

// ---------------- kernel 4: grouped GEMM2 (h @ W2, weighted scatter) ----------------
__global__ void __launch_bounds__(256, 2) k_gemm2(float* __restrict__ out){
    int e = g_tile_e[blockIdx.y];
    if (e < 0) return;
    int base = g_tile_base[blockIdx.y];
    int cnt  = g_cnt[e];
    int n0   = blockIdx.x * BN;

    __shared__ __align__(16) float As[2][BM][BK + 4];
    __shared__ __align__(16) float Bs[2][BK][BN + 8];
    __shared__ int   s_tok[BM];
    __shared__ float s_w[BM];

    int tid = threadIdx.x;
    if (tid < BM){
        int idx = base + tid;
        bool valid = idx < cnt;
        int ci = valid ? idx : (cnt - 1);
        s_tok[tid] = g_tok[e][ci];
        s_w[tid]   = valid ? g_wt[e][idx] : 0.f;
    }

    const float* wp = g_w2r + (size_t)e * INTER * HID;

    int arow = tid >> 2;
    int af4  = (tid & 3) * 4;
    int brow = tid >> 5;
    int bf4  = (tid & 31) * 4;

    long long hbase = (long long)blockIdx.y * BM;
    const float* a0p = g_h + (hbase + arow     ) * INTER + af4;
    const float* a1p = g_h + (hbase + arow + 64) * INTER + af4;

    float4 c[2][8];
#pragma unroll
    for (int mi = 0; mi < 2; mi++)
#pragma unroll
        for (int ni = 0; ni < 8; ni++) c[mi][ni] = make_float4(0.f, 0.f, 0.f, 0.f);

    int w    = tid >> 5;
    int lane = tid & 31;
    int wrow = (w & 3) * 32;
    int wcol = (w >> 2) * 64;
    int g    = lane >> 2;
    int q    = lane & 3;

    auto load_tile = [&](int buf, int k0){
        cp_async16(&As[buf][arow     ][af4], a0p + k0);
        cp_async16(&As[buf][arow + 64][af4], a1p + k0);
        cp_async16(&Bs[buf][brow     ][bf4], wp + (size_t)(k0 + brow    ) * HID + n0 + bf4);
        cp_async16(&Bs[buf][brow + 8 ][bf4], wp + (size_t)(k0 + brow + 8) * HID + n0 + bf4);
    };

    load_tile(0, 0);
    cp_commit();

    const int KT = INTER / BK;   // 256
    for (int it = 0; it < KT; it++){
        int cur = it & 1;
        if (it + 1 < KT) load_tile(cur ^ 1, (it + 1) * BK);
        cp_commit();
        cp_wait1();
        __syncthreads();
#pragma unroll
        for (int kk = 0; kk < 2; kk++){
            int ko = kk * 8;
            uint32_t a[2][4];
#pragma unroll
            for (int mi = 0; mi < 2; mi++){
                int rb = wrow + mi * 16;
                a[mi][0] = __float_as_uint(As[cur][rb + g    ][ko + q    ]);
                a[mi][1] = __float_as_uint(As[cur][rb + g + 8][ko + q    ]);
                a[mi][2] = __float_as_uint(As[cur][rb + g    ][ko + q + 4]);
                a[mi][3] = __float_as_uint(As[cur][rb + g + 8][ko + q + 4]);
            }
#pragma unroll
            for (int ni = 0; ni < 8; ni++){
                int col = wcol + ni * 8 + g;
                uint32_t b0 = __float_as_uint(Bs[cur][ko + q    ][col]);
                uint32_t b1 = __float_as_uint(Bs[cur][ko + q + 4][col]);
#pragma unroll
                for (int mi = 0; mi < 2; mi++)
                    mma8(c[mi][ni], a[mi][0], a[mi][1], a[mi][2], a[mi][3], b0, b1);
            }
        }
        __syncthreads();
    }

    // epilogue: weighted scatter-add into output
#pragma unroll
    for (int mi = 0; mi < 2; mi++){
        int r0 = wrow + mi * 16 + g;
        float wt0 = s_w[r0];     int tok0 = s_tok[r0];
        float wt1 = s_w[r0 + 8]; int tok1 = s_tok[r0 + 8];
#pragma unroll
        for (int ni = 0; ni < 8; ni++){
            int col = n0 + wcol + ni * 8 + q * 2;
            float4 v = c[mi][ni];
            if (wt0 != 0.f){
                atomicAdd(&out[(size_t)tok0 * HID + col    ], wt0 * v.x);
                atomicAdd(&out[(size_t)tok0 * HID + col + 1], wt0 * v.y);
            }
            if (wt1 != 0.f){
                atomicAdd(&out[(size_t)tok1 * HID + col    ], wt1 * v.z);
                atomicAdd(&out[(size_t)tok1 * HID + col + 1], wt1 * v.w);
            }
        }
    }
}

// ---------------- entry point ----------------
extern "C" void kernel_launch(void* const* d_in, const int* in_sizes, int n_in,
                              void* d_out, int out_size){
    const float* x  = (const float*)d_in[0];
    const float* rw = (const float*)d_in[1];
    const float* w1 = (const float*)d_in[2];
    const float* w2 = (const float*)d_in[3];
    float* out = (float*)d_out;

    k_init<<<2048, 256>>>(out, out_size);
    k_prep<<<2048, 256>>>(x, w1, w2);
    k_router<<<NT / 8, 256>>>(x, rw);
    k_setup<<<1, 32>>>(out, out_size);
    dim3 grid1(INTER / BN, MAX_TILES);
    k_gemm1<<<grid1, 256>>>(nullptr);
    dim3 grid2(HID / BN, MAX_TILES);
    k_gemm2<<<grid2, 256>>>(out);
}

// round 8
// speedup vs baseline: 2.4670x; 2.4670x over previous
#include <cuda_runtime.h>
#include <cuda_fp16.h>
#include <cstdint>

// Problem constants
constexpr int HID   = 1024;
constexpr int INTER = 4096;
constexpr int NE    = 8;
constexpr int NT    = 8192;

// Tiling
constexpr int BM = 128;
constexpr int BN = 128;
constexpr int BK = 32;                          // 32 halves = 64B per A-row chunk
constexpr int MAX_TILES = (2 * NT) / BM + NE;   // 136
constexpr int APITCH = 40;                      // halves; 80B rows -> ldmatrix conflict-free (5 coprime 8)
constexpr int BPITCH = BN + 8;                  // 136 halves; 272B rows -> conflict-free (17 coprime 8)

// ---------------- device scratch (no allocations allowed) ----------------
__device__ int    g_tok[NE][NT];
__device__ float  g_wt [NE][NT];
__device__ int    g_cnt[NE];
__device__ int    g_top1[NE];
__device__ float  g_psum[NE];
__device__ int    g_tile_e[MAX_TILES];
__device__ int    g_tile_base[MAX_TILES];
__device__ __half g_h  [(long long)MAX_TILES * BM * INTER];  // 142 MB fp16
__device__ __half g_xh [NT * HID];                           // 16 MB
__device__ __half g_w1h[(long long)NE * HID * INTER];        // 67 MB
__device__ __half g_w2h[(long long)NE * INTER * HID];        // 67 MB

// ---------------- helpers ----------------
__device__ __forceinline__ uint32_t smem_u32(const void* p){
    return (uint32_t)__cvta_generic_to_shared(p);
}
__device__ __forceinline__ void cp_async16(void* smem_dst, const void* gmem_src){
    asm volatile("cp.async.cg.shared.global [%0], [%1], 16;\n"
                 :: "r"(smem_u32(smem_dst)), "l"(gmem_src));
}
__device__ __forceinline__ void cp_commit(){ asm volatile("cp.async.commit_group;\n" ::: "memory"); }
__device__ __forceinline__ void cp_wait1(){ asm volatile("cp.async.wait_group 1;\n" ::: "memory"); }

__device__ __forceinline__ void ldsm4(uint32_t* r, uint32_t addr){
    asm volatile("ldmatrix.sync.aligned.m8n8.x4.shared.b16 {%0,%1,%2,%3}, [%4];\n"
                 : "=r"(r[0]), "=r"(r[1]), "=r"(r[2]), "=r"(r[3]) : "r"(addr));
}
__device__ __forceinline__ void ldsm4t(uint32_t* r, uint32_t addr){
    asm volatile("ldmatrix.sync.aligned.m8n8.x4.trans.shared.b16 {%0,%1,%2,%3}, [%4];\n"
                 : "=r"(r[0]), "=r"(r[1]), "=r"(r[2]), "=r"(r[3]) : "r"(addr));
}
__device__ __forceinline__ void mma16(float4& d, const uint32_t* a, const uint32_t* b){
    asm volatile("mma.sync.aligned.m16n8k16.row.col.f32.f16.f16.f32 "
                 "{%0,%1,%2,%3}, {%4,%5,%6,%7}, {%8,%9}, {%0,%1,%2,%3};\n"
                 : "+f"(d.x), "+f"(d.y), "+f"(d.z), "+f"(d.w)
                 : "r"(a[0]), "r"(a[1]), "r"(a[2]), "r"(a[3]), "r"(b[0]), "r"(b[1]));
}

// ---------------- kernel 0: zero output + counters ----------------
__global__ void k_init(float* out, int n){
    int stride = gridDim.x * blockDim.x;
    for (int i = blockIdx.x * blockDim.x + threadIdx.x; i < n; i += stride) out[i] = 0.f;
    if (blockIdx.x == 0 && threadIdx.x < NE){
        g_cnt[threadIdx.x]  = 0;
        g_top1[threadIdx.x] = 0;
        g_psum[threadIdx.x] = 0.f;
    }
}

// ---------------- kernel 0b: convert x / W1 / W2 to fp16 ----------------
__device__ __forceinline__ void conv8(const float4* s, uint4* d, long long i){
    float4 v0 = s[i * 2], v1 = s[i * 2 + 1];
    __half2 h0 = __floats2half2_rn(v0.x, v0.y);
    __half2 h1 = __floats2half2_rn(v0.z, v0.w);
    __half2 h2 = __floats2half2_rn(v1.x, v1.y);
    __half2 h3 = __floats2half2_rn(v1.z, v1.w);
    uint4 o;
    o.x = *reinterpret_cast<uint32_t*>(&h0);
    o.y = *reinterpret_cast<uint32_t*>(&h1);
    o.z = *reinterpret_cast<uint32_t*>(&h2);
    o.w = *reinterpret_cast<uint32_t*>(&h3);
    d[i] = o;
}

__global__ void k_prep(const float* __restrict__ x,
                       const float* __restrict__ w1,
                       const float* __restrict__ w2){
    long long stride = (long long)gridDim.x * blockDim.x;
    long long t0 = (long long)blockIdx.x * blockDim.x + threadIdx.x;

    const long long NX = (long long)NT * HID / 8;
    const long long NW = (long long)NE * HID * INTER / 8;

    const float4* xs = reinterpret_cast<const float4*>(x);
    uint4* xd = reinterpret_cast<uint4*>(g_xh);
    for (long long i = t0; i < NX; i += stride) conv8(xs, xd, i);

    const float4* w1s = reinterpret_cast<const float4*>(w1);
    uint4* w1d = reinterpret_cast<uint4*>(g_w1h);
    for (long long i = t0; i < NW; i += stride) conv8(w1s, w1d, i);

    const float4* w2s = reinterpret_cast<const float4*>(w2);
    uint4* w2d = reinterpret_cast<uint4*>(g_w2h);
    for (long long i = t0; i < NW; i += stride) conv8(w2s, w2d, i);
}

// ---------------- kernel 1: router (1 warp per token) ----------------
__global__ void k_router(const float* __restrict__ x, const float* __restrict__ rw){
    int t = blockIdx.x * (blockDim.x >> 5) + (threadIdx.x >> 5);
    int lane = threadIdx.x & 31;
    if (t >= NT) return;
    const float4* xr = reinterpret_cast<const float4*>(x + (size_t)t * HID);
    float acc[NE];
#pragma unroll
    for (int e = 0; e < NE; e++) acc[e] = 0.f;
#pragma unroll
    for (int j = 0; j < 8; j++){
        float4 xv = xr[lane + 32 * j];
#pragma unroll
        for (int e = 0; e < NE; e++){
            float4 wv = reinterpret_cast<const float4*>(rw + e * HID)[lane + 32 * j];
            acc[e] += xv.x * wv.x + xv.y * wv.y + xv.z * wv.z + xv.w * wv.w;
        }
    }
#pragma unroll
    for (int o = 16; o > 0; o >>= 1)
#pragma unroll
        for (int e = 0; e < NE; e++)
            acc[e] += __shfl_xor_sync(0xffffffffu, acc[e], o);

    if (lane == 0){
        float m = acc[0];
#pragma unroll
        for (int e = 1; e < NE; e++) m = fmaxf(m, acc[e]);
        float p[NE]; float s = 0.f;
#pragma unroll
        for (int e = 0; e < NE; e++){ p[e] = expf(acc[e] - m); s += p[e]; }
        float inv = 1.f / s;
#pragma unroll
        for (int e = 0; e < NE; e++) p[e] *= inv;
        // top-2 (ties -> lower index, matching jax top_k)
        int i1 = 0;
#pragma unroll
        for (int e = 1; e < NE; e++) if (p[e] > p[i1]) i1 = e;
        int i2 = (i1 == 0) ? 1 : 0;
#pragma unroll
        for (int e = 0; e < NE; e++) if (e != i1 && p[e] > p[i2]) i2 = e;
        float w1 = p[i1], w2 = p[i2];
        float rs = 1.f / (w1 + w2);
        w1 *= rs; w2 *= rs;
        int pos1 = atomicAdd(&g_cnt[i1], 1);
        g_tok[i1][pos1] = t; g_wt[i1][pos1] = w1;
        int pos2 = atomicAdd(&g_cnt[i2], 1);
        g_tok[i2][pos2] = t; g_wt[i2][pos2] = w2;
        atomicAdd(&g_top1[i1], 1);
#pragma unroll
        for (int e = 0; e < NE; e++) atomicAdd(&g_psum[e], p[e]);
    }
}

// ---------------- kernel 2: tile map + aux loss ----------------
__global__ void k_setup(float* out, int out_size){
    if (threadIdx.x != 0 || blockIdx.x != 0) return;
    int nt = 0;
    for (int e = 0; e < NE; e++){
        int c = g_cnt[e];
        for (int b = 0; b < c; b += BM){
            g_tile_e[nt] = e; g_tile_base[nt] = b; nt++;
        }
    }
    for (; nt < MAX_TILES; nt++) g_tile_e[nt] = -1;

    float aux = 0.f;
    for (int e = 0; e < NE; e++)
        aux += ((float)g_top1[e] / (float)NT) * (g_psum[e] / (float)NT);
    aux *= (float)NE;
    if (out_size > NT * HID) out[NT * HID] = aux;
}

// ---------------- kernel 3: grouped GEMM1 (gather x @ W1, SiLU) fp16 ----------------
__global__ void __launch_bounds__(256, 2) k_gemm1(){
    int e = g_tile_e[blockIdx.y];
    if (e < 0) return;
    int base = g_tile_base[blockIdx.y];
    int cnt  = g_cnt[e];
    int n0   = blockIdx.x * BN;

    __shared__ __align__(16) __half As[2][BM][APITCH];
    __shared__ __align__(16) __half Bs[2][BK][BPITCH];
    __shared__ int s_tok[BM];

    int tid = threadIdx.x;
    if (tid < BM){
        int idx = base + tid;
        if (idx >= cnt) idx = cnt - 1;
        s_tok[tid] = g_tok[e][idx];
    }
    __syncthreads();

    const __half* wp = g_w1h + (size_t)e * HID * INTER;

    int arow = tid >> 1;             // 0..127, 2 threads/row
    int ach  = (tid & 1) * 16;       // half-offset 0 or 16
    int brow = tid >> 3;             // 0..31, 8 threads/row
    int bch  = (tid & 7) * 16;       // half-offset 0..112

    const __half* asrc = g_xh + (size_t)s_tok[arow] * HID + ach;

    float4 c[2][8];
#pragma unroll
    for (int mi = 0; mi < 2; mi++)
#pragma unroll
        for (int ni = 0; ni < 8; ni++) c[mi][ni] = make_float4(0.f, 0.f, 0.f, 0.f);

    int w    = tid >> 5;
    int lane = tid & 31;
    int wrow = (w & 3) * 32;
    int wcol = (w >> 2) * 64;
    int g    = lane >> 2;
    int q    = lane & 3;

    auto load_tile = [&](int buf, int k0){
        cp_async16(&As[buf][arow][ach    ], asrc + k0);
        cp_async16(&As[buf][arow][ach + 8], asrc + k0 + 8);
        const __half* bsrc = wp + (size_t)(k0 + brow) * INTER + n0 + bch;
        cp_async16(&Bs[buf][brow][bch    ], bsrc);
        cp_async16(&Bs[buf][brow][bch + 8], bsrc + 8);
    };

    load_tile(0, 0);
    cp_commit();

    const int KT = HID / BK;   // 32
    for (int it = 0; it < KT; it++){
        int cur = it & 1;
        if (it + 1 < KT) load_tile(cur ^ 1, (it + 1) * BK);
        cp_commit();
        cp_wait1();
        __syncthreads();
#pragma unroll
        for (int kk = 0; kk < 2; kk++){
            int ko = kk * 16;
            uint32_t a[2][4];
#pragma unroll
            for (int mi = 0; mi < 2; mi++){
                uint32_t addr = smem_u32(&As[cur][wrow + mi * 16 + (lane & 15)][ko + (lane >> 4) * 8]);
                ldsm4(a[mi], addr);
            }
            uint32_t b[8][2];
#pragma unroll
            for (int np = 0; np < 4; np++){
                int krow = ko + ((lane >> 3) & 1) * 8 + (lane & 7);
                int ncol = wcol + np * 16 + ((lane >> 4) & 1) * 8;
                uint32_t t[4];
                ldsm4t(t, smem_u32(&Bs[cur][krow][ncol]));
                b[np * 2    ][0] = t[0]; b[np * 2    ][1] = t[1];
                b[np * 2 + 1][0] = t[2]; b[np * 2 + 1][1] = t[3];
            }
#pragma unroll
            for (int ni = 0; ni < 8; ni++)
#pragma unroll
                for (int mi = 0; mi < 2; mi++)
                    mma16(c[mi][ni], a[mi], b[ni]);
        }
        __syncthreads();
    }

    // epilogue: SiLU, store fp16 h
    long long hbase = (long long)blockIdx.y * BM;
#pragma unroll
    for (int mi = 0; mi < 2; mi++){
        int r0 = wrow + mi * 16 + g;
#pragma unroll
        for (int ni = 0; ni < 8; ni++){
            int col = n0 + wcol + ni * 8 + q * 2;
            float4 v = c[mi][ni];
            float s0 = v.x / (1.f + __expf(-v.x));
            float s1 = v.y / (1.f + __expf(-v.y));
            float s2 = v.z / (1.f + __expf(-v.z));
            float s3 = v.w / (1.f + __expf(-v.w));
            *reinterpret_cast<__half2*>(&g_h[(hbase + r0    ) * INTER + col]) = __floats2half2_rn(s0, s1);
            *reinterpret_cast<__half2*>(&g_h[(hbase + r0 + 8) * INTER + col]) = __floats2half2_rn(s2, s3);
        }
    }
}

// ---------------- kernel 4: grouped GEMM2 (h @ W2, weighted scatter) fp16 ----------------
__global__ void __launch_bounds__(256, 2) k_gemm2(float* __restrict__ out){
    int e = g_tile_e[blockIdx.y];
    if (e < 0) return;
    int base = g_tile_base[blockIdx.y];
    int cnt  = g_cnt[e];
    int n0   = blockIdx.x * BN;

    __shared__ __align__(16) __half As[2][BM][APITCH];
    __shared__ __align__(16) __half Bs[2][BK][BPITCH];
    __shared__ int   s_tok[BM];
    __shared__ float s_w[BM];

    int tid = threadIdx.x;
    if (tid < BM){
        int idx = base + tid;
        bool valid = idx < cnt;
        int ci = valid ? idx : (cnt - 1);
        s_tok[tid] = g_tok[e][ci];
        s_w[tid]   = valid ? g_wt[e][idx] : 0.f;
    }
    __syncthreads();

    const __half* wp = g_w2h + (size_t)e * INTER * HID;

    int arow = tid >> 1;
    int ach  = (tid & 1) * 16;
    int brow = tid >> 3;
    int bch  = (tid & 7) * 16;

    long long hbase = (long long)blockIdx.y * BM;
    const __half* asrc = g_h + (hbase + arow) * INTER + ach;

    float4 c[2][8];
#pragma unroll
    for (int mi = 0; mi < 2; mi++)
#pragma unroll
        for (int ni = 0; ni < 8; ni++) c[mi][ni] = make_float4(0.f, 0.f, 0.f, 0.f);

    int w    = tid >> 5;
    int lane = tid & 31;
    int wrow = (w & 3) * 32;
    int wcol = (w >> 2) * 64;
    int g    = lane >> 2;
    int q    = lane & 3;

    auto load_tile = [&](int buf, int k0){
        cp_async16(&As[buf][arow][ach    ], asrc + k0);
        cp_async16(&As[buf][arow][ach + 8], asrc + k0 + 8);
        const __half* bsrc = wp + (size_t)(k0 + brow) * HID + n0 + bch;
        cp_async16(&Bs[buf][brow][bch    ], bsrc);
        cp_async16(&Bs[buf][brow][bch + 8], bsrc + 8);
    };

    load_tile(0, 0);
    cp_commit();

    const int KT = INTER / BK;   // 128
    for (int it = 0; it < KT; it++){
        int cur = it & 1;
        if (it + 1 < KT) load_tile(cur ^ 1, (it + 1) * BK);
        cp_commit();
        cp_wait1();
        __syncthreads();
#pragma unroll
        for (int kk = 0; kk < 2; kk++){
            int ko = kk * 16;
            uint32_t a[2][4];
#pragma unroll
            for (int mi = 0; mi < 2; mi++){
                uint32_t addr = smem_u32(&As[cur][wrow + mi * 16 + (lane & 15)][ko + (lane >> 4) * 8]);
                ldsm4(a[mi], addr);
            }
            uint32_t b[8][2];
#pragma unroll
            for (int np = 0; np < 4; np++){
                int krow = ko + ((lane >> 3) & 1) * 8 + (lane & 7);
                int ncol = wcol + np * 16 + ((lane >> 4) & 1) * 8;
                uint32_t t[4];
                ldsm4t(t, smem_u32(&Bs[cur][krow][ncol]));
                b[np * 2    ][0] = t[0]; b[np * 2    ][1] = t[1];
                b[np * 2 + 1][0] = t[2]; b[np * 2 + 1][1] = t[3];
            }
#pragma unroll
            for (int ni = 0; ni < 8; ni++)
#pragma unroll
                for (int mi = 0; mi < 2; mi++)
                    mma16(c[mi][ni], a[mi], b[ni]);
        }
        __syncthreads();
    }

    // epilogue: weighted scatter-add into output
#pragma unroll
    for (int mi = 0; mi < 2; mi++){
        int r0 = wrow + mi * 16 + g;
        float wt0 = s_w[r0];     int tok0 = s_tok[r0];
        float wt1 = s_w[r0 + 8]; int tok1 = s_tok[r0 + 8];
#pragma unroll
        for (int ni = 0; ni < 8; ni++){
            int col = n0 + wcol + ni * 8 + q * 2;
            float4 v = c[mi][ni];
            if (wt0 != 0.f){
                atomicAdd(&out[(size_t)tok0 * HID + col    ], wt0 * v.x);
                atomicAdd(&out[(size_t)tok0 * HID + col + 1], wt0 * v.y);
            }
            if (wt1 != 0.f){
                atomicAdd(&out[(size_t)tok1 * HID + col    ], wt1 * v.z);
                atomicAdd(&out[(size_t)tok1 * HID + col + 1], wt1 * v.w);
            }
        }
    }
}

// ---------------- entry point ----------------
extern "C" void kernel_launch(void* const* d_in, const int* in_sizes, int n_in,
                              void* d_out, int out_size){
    const float* x  = (const float*)d_in[0];
    const float* rw = (const float*)d_in[1];
    const float* w1 = (const float*)d_in[2];
    const float* w2 = (const float*)d_in[3];
    float* out = (float*)d_out;

    k_init<<<2048, 256>>>(out, out_size);
    k_prep<<<2048, 256>>>(x, w1, w2);
    k_router<<<NT / 8, 256>>>(x, rw);
    k_setup<<<1, 32>>>(out, out_size);
    dim3 grid1(INTER / BN, MAX_TILES);
    k_gemm1<<<grid1, 256>>>();
    dim3 grid2(HID / BN, MAX_TILES);
    k_gemm2<<<grid2, 256>>>(out);
}

// round 11
// speedup vs baseline: 2.5901x; 1.0499x over previous
#include <cuda_runtime.h>
#include <cuda_fp16.h>
#include <cstdint>

// Problem constants
constexpr int HID   = 1024;
constexpr int INTER = 4096;
constexpr int NE    = 8;
constexpr int NT    = 8192;

// Tiling
constexpr int BM = 128;
constexpr int BN = 128;
constexpr int BK = 32;                          // halves per k-tile
constexpr int NS = 4;                           // cp.async pipeline stages
constexpr int MAX_TILES = (2 * NT) / BM + NE;   // 136
constexpr int NROWS = MAX_TILES * BM;           // 17408 padded pair-rows
constexpr int APITCH = 40;                      // halves; 80B rows (5 coprime 8 -> ldsm conflict-free)
constexpr int BPITCH = BN + 8;                  // 136 halves; 272B rows (17 coprime 8)
constexpr int ASTAGE = BM * APITCH * 2;         // 10240 B
constexpr int BSTAGE = BK * BPITCH * 2;         // 8704 B
constexpr int SMEM_DYN = NS * (ASTAGE + BSTAGE);// 75776 B

// ---------------- device scratch (no allocations allowed) ----------------
__device__ int    g_tok[NE][NT];
__device__ float  g_wt [NE][NT];
__device__ int    g_cnt[NE];
__device__ int    g_top1[NE];
__device__ float  g_psum[NE];
__device__ int    g_tile_e[MAX_TILES];
__device__ int    g_tile_base[MAX_TILES];
__device__ int    g_tile_start[NE];
__device__ int    g_slot_e[NT][2];
__device__ int    g_slot_p[NT][2];
__device__ __half g_h  [(long long)NROWS * INTER];    // 142 MB fp16 hidden
__device__ float  g_y  [(long long)NROWS * HID];      // 71 MB fp32 pre-combine
__device__ __half g_xh [NT * HID];
__device__ __half g_w1h[(long long)NE * HID * INTER];
__device__ __half g_w2h[(long long)NE * INTER * HID];

// ---------------- helpers ----------------
__device__ __forceinline__ uint32_t smem_u32(const void* p){
    return (uint32_t)__cvta_generic_to_shared(p);
}
__device__ __forceinline__ void cp_async16(uint32_t smem_dst, const void* gmem_src){
    asm volatile("cp.async.cg.shared.global [%0], [%1], 16;\n" :: "r"(smem_dst), "l"(gmem_src));
}
__device__ __forceinline__ void cp_commit(){ asm volatile("cp.async.commit_group;\n" ::: "memory"); }
#define CP_WAIT_GROUP(n) asm volatile("cp.async.wait_group %0;\n" :: "n"(n) : "memory")

__device__ __forceinline__ void ldsm4(uint32_t* r, uint32_t addr){
    asm volatile("ldmatrix.sync.aligned.m8n8.x4.shared.b16 {%0,%1,%2,%3}, [%4];\n"
                 : "=r"(r[0]), "=r"(r[1]), "=r"(r[2]), "=r"(r[3]) : "r"(addr));
}
__device__ __forceinline__ void ldsm4t(uint32_t* r, uint32_t addr){
    asm volatile("ldmatrix.sync.aligned.m8n8.x4.trans.shared.b16 {%0,%1,%2,%3}, [%4];\n"
                 : "=r"(r[0]), "=r"(r[1]), "=r"(r[2]), "=r"(r[3]) : "r"(addr));
}
__device__ __forceinline__ void mma16(float4& d, const uint32_t* a, const uint32_t* b){
    asm volatile("mma.sync.aligned.m16n8k16.row.col.f32.f16.f16.f32 "
                 "{%0,%1,%2,%3}, {%4,%5,%6,%7}, {%8,%9}, {%0,%1,%2,%3};\n"
                 : "+f"(d.x), "+f"(d.y), "+f"(d.z), "+f"(d.w)
                 : "r"(a[0]), "r"(a[1]), "r"(a[2]), "r"(a[3]), "r"(b[0]), "r"(b[1]));
}

// ---------------- kernel 0: counters + output tail ----------------
__global__ void k_init(float* out, int n){
    if (blockIdx.x == 0 && threadIdx.x < NE){
        g_cnt[threadIdx.x]  = 0;
        g_top1[threadIdx.x] = 0;
        g_psum[threadIdx.x] = 0.f;
    }
    for (int i = NT * HID + blockIdx.x * blockDim.x + threadIdx.x; i < n;
         i += gridDim.x * blockDim.x) out[i] = 0.f;
}

// ---------------- kernel 0b: convert x / W1 / W2 to fp16 ----------------
__device__ __forceinline__ void conv8(const float4* s, uint4* d, long long i){
    float4 v0 = s[i * 2], v1 = s[i * 2 + 1];
    __half2 h0 = __floats2half2_rn(v0.x, v0.y);
    __half2 h1 = __floats2half2_rn(v0.z, v0.w);
    __half2 h2 = __floats2half2_rn(v1.x, v1.y);
    __half2 h3 = __floats2half2_rn(v1.z, v1.w);
    uint4 o;
    o.x = *reinterpret_cast<uint32_t*>(&h0);
    o.y = *reinterpret_cast<uint32_t*>(&h1);
    o.z = *reinterpret_cast<uint32_t*>(&h2);
    o.w = *reinterpret_cast<uint32_t*>(&h3);
    d[i] = o;
}

__global__ void k_prep(const float* __restrict__ x,
                       const float* __restrict__ w1,
                       const float* __restrict__ w2){
    long long stride = (long long)gridDim.x * blockDim.x;
    long long t0 = (long long)blockIdx.x * blockDim.x + threadIdx.x;
    const long long NX = (long long)NT * HID / 8;
    const long long NW = (long long)NE * HID * INTER / 8;

    const float4* xs = reinterpret_cast<const float4*>(x);
    uint4* xd = reinterpret_cast<uint4*>(g_xh);
    for (long long i = t0; i < NX; i += stride) conv8(xs, xd, i);

    const float4* w1s = reinterpret_cast<const float4*>(w1);
    uint4* w1d = reinterpret_cast<uint4*>(g_w1h);
    for (long long i = t0; i < NW; i += stride) conv8(w1s, w1d, i);

    const float4* w2s = reinterpret_cast<const float4*>(w2);
    uint4* w2d = reinterpret_cast<uint4*>(g_w2h);
    for (long long i = t0; i < NW; i += stride) conv8(w2s, w2d, i);
}

// ---------------- kernel 1: router ----------------
__global__ void k_router(const float* __restrict__ x, const float* __restrict__ rw){
    int t = blockIdx.x * (blockDim.x >> 5) + (threadIdx.x >> 5);
    int lane = threadIdx.x & 31;
    if (t >= NT) return;
    const float4* xr = reinterpret_cast<const float4*>(x + (size_t)t * HID);
    float acc[NE];
#pragma unroll
    for (int e = 0; e < NE; e++) acc[e] = 0.f;
#pragma unroll
    for (int j = 0; j < 8; j++){
        float4 xv = xr[lane + 32 * j];
#pragma unroll
        for (int e = 0; e < NE; e++){
            float4 wv = reinterpret_cast<const float4*>(rw + e * HID)[lane + 32 * j];
            acc[e] += xv.x * wv.x + xv.y * wv.y + xv.z * wv.z + xv.w * wv.w;
        }
    }
#pragma unroll
    for (int o = 16; o > 0; o >>= 1)
#pragma unroll
        for (int e = 0; e < NE; e++)
            acc[e] += __shfl_xor_sync(0xffffffffu, acc[e], o);

    if (lane == 0){
        float m = acc[0];
#pragma unroll
        for (int e = 1; e < NE; e++) m = fmaxf(m, acc[e]);
        float p[NE]; float s = 0.f;
#pragma unroll
        for (int e = 0; e < NE; e++){ p[e] = expf(acc[e] - m); s += p[e]; }
        float inv = 1.f / s;
#pragma unroll
        for (int e = 0; e < NE; e++) p[e] *= inv;
        int i1 = 0;
#pragma unroll
        for (int e = 1; e < NE; e++) if (p[e] > p[i1]) i1 = e;
        int i2 = (i1 == 0) ? 1 : 0;
#pragma unroll
        for (int e = 0; e < NE; e++) if (e != i1 && p[e] > p[i2]) i2 = e;
        float w1 = p[i1], w2 = p[i2];
        float rs = 1.f / (w1 + w2);
        w1 *= rs; w2 *= rs;
        int pos1 = atomicAdd(&g_cnt[i1], 1);
        g_tok[i1][pos1] = t; g_wt[i1][pos1] = w1;
        int pos2 = atomicAdd(&g_cnt[i2], 1);
        g_tok[i2][pos2] = t; g_wt[i2][pos2] = w2;
        g_slot_e[t][0] = i1; g_slot_p[t][0] = pos1;
        g_slot_e[t][1] = i2; g_slot_p[t][1] = pos2;
        atomicAdd(&g_top1[i1], 1);
#pragma unroll
        for (int e = 0; e < NE; e++) atomicAdd(&g_psum[e], p[e]);
    }
}

// ---------------- kernel 2: tile map + aux ----------------
__global__ void k_setup(float* out, int out_size){
    if (threadIdx.x != 0 || blockIdx.x != 0) return;
    int nt = 0;
    for (int e = 0; e < NE; e++){
        g_tile_start[e] = nt;
        int c = g_cnt[e];
        for (int b = 0; b < c; b += BM){
            g_tile_e[nt] = e; g_tile_base[nt] = b; nt++;
        }
    }
    for (; nt < MAX_TILES; nt++) g_tile_e[nt] = -1;

    float aux = 0.f;
    for (int e = 0; e < NE; e++)
        aux += ((float)g_top1[e] / (float)NT) * (g_psum[e] / (float)NT);
    aux *= (float)NE;
    if (out_size > NT * HID) out[NT * HID] = aux;
}

// ---------------- kernel 3: grouped GEMM1 (gather x @ W1, SiLU) ----------------
__global__ void __launch_bounds__(256, 2) k_gemm1(){
    extern __shared__ __align__(16) char dsm[];
    __shared__ int s_tok[BM];

    int e = g_tile_e[blockIdx.y];
    if (e < 0) return;
    int base = g_tile_base[blockIdx.y];
    int cnt  = g_cnt[e];
    int n0   = blockIdx.x * BN;

    int tid = threadIdx.x;
    if (tid < BM){
        int idx = base + tid;
        if (idx >= cnt) idx = cnt - 1;
        s_tok[tid] = g_tok[e][idx];
    }
    __syncthreads();

    const __half* wp = g_w1h + (size_t)e * HID * INTER;

    int arow = tid >> 1, ach = (tid & 1) * 16;
    int brow = tid >> 3, bch = (tid & 7) * 16;
    const __half* asrc = g_xh + (size_t)s_tok[arow] * HID + ach;

    __half* Abase = reinterpret_cast<__half*>(dsm);
    __half* Bbase = reinterpret_cast<__half*>(dsm + NS * ASTAGE);

    auto load_tile = [&](int s, int k0){
        __half* A = Abase + (size_t)s * BM * APITCH;
        __half* B = Bbase + (size_t)s * BK * BPITCH;
        cp_async16(smem_u32(&A[arow * APITCH + ach    ]), asrc + k0);
        cp_async16(smem_u32(&A[arow * APITCH + ach + 8]), asrc + k0 + 8);
        const __half* bs = wp + (size_t)(k0 + brow) * INTER + n0 + bch;
        cp_async16(smem_u32(&B[brow * BPITCH + bch    ]), bs);
        cp_async16(smem_u32(&B[brow * BPITCH + bch + 8]), bs + 8);
    };

#pragma unroll
    for (int j = 0; j < NS - 1; j++){ load_tile(j, j * BK); cp_commit(); }

    float4 c[2][8];
#pragma unroll
    for (int mi = 0; mi < 2; mi++)
#pragma unroll
        for (int ni = 0; ni < 8; ni++) c[mi][ni] = make_float4(0.f, 0.f, 0.f, 0.f);

    int w    = tid >> 5;
    int lane = tid & 31;
    int wrow = (w & 3) * 32;
    int wcol = (w >> 2) * 64;
    int g    = lane >> 2;
    int q    = lane & 3;

    const int KT = HID / BK;   // 32
    for (int it = 0; it < KT; it++){
        CP_WAIT_GROUP(2);
        __syncthreads();
        int nxt = it + NS - 1;
        if (nxt < KT) load_tile(nxt & 3, nxt * BK);
        cp_commit();
        __half* A = Abase + (size_t)(it & 3) * BM * APITCH;
        __half* B = Bbase + (size_t)(it & 3) * BK * BPITCH;
#pragma unroll
        for (int kk = 0; kk < 2; kk++){
            int ko = kk * 16;
            uint32_t a[2][4];
#pragma unroll
            for (int mi = 0; mi < 2; mi++)
                ldsm4(a[mi], smem_u32(&A[(wrow + mi * 16 + (lane & 15)) * APITCH + ko + (lane >> 4) * 8]));
            uint32_t b[8][2];
#pragma unroll
            for (int np = 0; np < 4; np++){
                int krow = ko + ((lane >> 3) & 1) * 8 + (lane & 7);
                int ncol = wcol + np * 16 + ((lane >> 4) & 1) * 8;
                uint32_t t[4];
                ldsm4t(t, smem_u32(&B[krow * BPITCH + ncol]));
                b[np * 2    ][0] = t[0]; b[np * 2    ][1] = t[1];
                b[np * 2 + 1][0] = t[2]; b[np * 2 + 1][1] = t[3];
            }
#pragma unroll
            for (int ni = 0; ni < 8; ni++)
#pragma unroll
                for (int mi = 0; mi < 2; mi++)
                    mma16(c[mi][ni], a[mi], b[ni]);
        }
    }

    // epilogue: SiLU, store fp16 h
    long long hbase = (long long)blockIdx.y * BM;
#pragma unroll
    for (int mi = 0; mi < 2; mi++){
        int r0 = wrow + mi * 16 + g;
#pragma unroll
        for (int ni = 0; ni < 8; ni++){
            int col = n0 + wcol + ni * 8 + q * 2;
            float4 v = c[mi][ni];
            float s0 = v.x / (1.f + __expf(-v.x));
            float s1 = v.y / (1.f + __expf(-v.y));
            float s2 = v.z / (1.f + __expf(-v.z));
            float s3 = v.w / (1.f + __expf(-v.w));
            *reinterpret_cast<__half2*>(&g_h[(hbase + r0    ) * INTER + col]) = __floats2half2_rn(s0, s1);
            *reinterpret_cast<__half2*>(&g_h[(hbase + r0 + 8) * INTER + col]) = __floats2half2_rn(s2, s3);
        }
    }
}

// ---------------- kernel 4: grouped GEMM2 (h @ W2, dense store) ----------------
__global__ void __launch_bounds__(256, 2) k_gemm2(){
    extern __shared__ __align__(16) char dsm[];

    int e = g_tile_e[blockIdx.y];
    if (e < 0) return;
    int n0 = blockIdx.x * BN;

    int tid = threadIdx.x;
    const __half* wp = g_w2h + (size_t)e * INTER * HID;

    int arow = tid >> 1, ach = (tid & 1) * 16;
    int brow = tid >> 3, bch = (tid & 7) * 16;

    long long hbase = (long long)blockIdx.y * BM;
    const __half* asrc = g_h + (hbase + arow) * INTER + ach;

    __half* Abase = reinterpret_cast<__half*>(dsm);
    __half* Bbase = reinterpret_cast<__half*>(dsm + NS * ASTAGE);

    auto load_tile = [&](int s, int k0){
        __half* A = Abase + (size_t)s * BM * APITCH;
        __half* B = Bbase + (size_t)s * BK * BPITCH;
        cp_async16(smem_u32(&A[arow * APITCH + ach    ]), asrc + k0);
        cp_async16(smem_u32(&A[arow * APITCH + ach + 8]), asrc + k0 + 8);
        const __half* bs = wp + (size_t)(k0 + brow) * HID + n0 + bch;
        cp_async16(smem_u32(&B[brow * BPITCH + bch    ]), bs);
        cp_async16(smem_u32(&B[brow * BPITCH + bch + 8]), bs + 8);
    };

#pragma unroll
    for (int j = 0; j < NS - 1; j++){ load_tile(j, j * BK); cp_commit(); }

    float4 c[2][8];
#pragma unroll
    for (int mi = 0; mi < 2; mi++)
#pragma unroll
        for (int ni = 0; ni < 8; ni++) c[mi][ni] = make_float4(0.f, 0.f, 0.f, 0.f);

    int w    = tid >> 5;
    int lane = tid & 31;
    int wrow = (w & 3) * 32;
    int wcol = (w >> 2) * 64;
    int g    = lane >> 2;
    int q    = lane & 3;

    const int KT = INTER / BK;   // 128
    for (int it = 0; it < KT; it++){
        CP_WAIT_GROUP(2);
        __syncthreads();
        int nxt = it + NS - 1;
        if (nxt < KT) load_tile(nxt & 3, nxt * BK);
        cp_commit();
        __half* A = Abase + (size_t)(it & 3) * BM * APITCH;
        __half* B = Bbase + (size_t)(it & 3) * BK * BPITCH;
#pragma unroll
        for (int kk = 0; kk < 2; kk++){
            int ko = kk * 16;
            uint32_t a[2][4];
#pragma unroll
            for (int mi = 0; mi < 2; mi++)
                ldsm4(a[mi], smem_u32(&A[(wrow + mi * 16 + (lane & 15)) * APITCH + ko + (lane >> 4) * 8]));
            uint32_t b[8][2];
#pragma unroll
            for (int np = 0; np < 4; np++){
                int krow = ko + ((lane >> 3) & 1) * 8 + (lane & 7);
                int ncol = wcol + np * 16 + ((lane >> 4) & 1) * 8;
                uint32_t t[4];
                ldsm4t(t, smem_u32(&B[krow * BPITCH + ncol]));
                b[np * 2    ][0] = t[0]; b[np * 2    ][1] = t[1];
                b[np * 2 + 1][0] = t[2]; b[np * 2 + 1][1] = t[3];
            }
#pragma unroll
            for (int ni = 0; ni < 8; ni++)
#pragma unroll
                for (int mi = 0; mi < 2; mi++)
                    mma16(c[mi][ni], a[mi], b[ni]);
        }
    }

    // epilogue: dense fp32 store (no atomics)
#pragma unroll
    for (int mi = 0; mi < 2; mi++){
        int r0 = wrow + mi * 16 + g;
#pragma unroll
        for (int ni = 0; ni < 8; ni++){
            int col = n0 + wcol + ni * 8 + q * 2;
            float4 v = c[mi][ni];
            float2 f0 = make_float2(v.x, v.y);
            float2 f1 = make_float2(v.z, v.w);
            *reinterpret_cast<float2*>(&g_y[(hbase + r0    ) * HID + col]) = f0;
            *reinterpret_cast<float2*>(&g_y[(hbase + r0 + 8) * HID + col]) = f1;
        }
    }
}

// ---------------- kernel 5: weighted combine ----------------
__global__ void k_combine(float* __restrict__ out){
    int t = blockIdx.x, tid = threadIdx.x;
    int e0 = g_slot_e[t][0], p0 = g_slot_p[t][0];
    int e1 = g_slot_e[t][1], p1 = g_slot_p[t][1];
    float w0 = g_wt[e0][p0], w1 = g_wt[e1][p1];
    long long r0 = (long long)(g_tile_start[e0] * BM + p0) * HID;
    long long r1 = (long long)(g_tile_start[e1] * BM + p1) * HID;
    const float4* y0 = reinterpret_cast<const float4*>(g_y + r0);
    const float4* y1 = reinterpret_cast<const float4*>(g_y + r1);
    float4 a = y0[tid], b = y1[tid];
    float4 o;
    o.x = w0 * a.x + w1 * b.x;
    o.y = w0 * a.y + w1 * b.y;
    o.z = w0 * a.z + w1 * b.z;
    o.w = w0 * a.w + w1 * b.w;
    reinterpret_cast<float4*>(out + (size_t)t * HID)[tid] = o;
}

// ---------------- entry point ----------------
extern "C" void kernel_launch(void* const* d_in, const int* in_sizes, int n_in,
                              void* d_out, int out_size){
    const float* x  = (const float*)d_in[0];
    const float* rw = (const float*)d_in[1];
    const float* w1 = (const float*)d_in[2];
    const float* w2 = (const float*)d_in[3];
    float* out = (float*)d_out;

    static bool attr_set = false;
    if (!attr_set){
        cudaFuncSetAttribute(k_gemm1, cudaFuncAttributeMaxDynamicSharedMemorySize, SMEM_DYN);
        cudaFuncSetAttribute(k_gemm2, cudaFuncAttributeMaxDynamicSharedMemorySize, SMEM_DYN);
        attr_set = true;
    }

    k_init<<<16, 256>>>(out, out_size);
    k_prep<<<2048, 256>>>(x, w1, w2);
    k_router<<<NT / 8, 256>>>(x, rw);
    k_setup<<<1, 32>>>(out, out_size);
    k_gemm1<<<dim3(INTER / BN, MAX_TILES), 256, SMEM_DYN>>>();
    k_gemm2<<<dim3(HID / BN, MAX_TILES), 256, SMEM_DYN>>>();
    k_combine<<<NT, 256>>>(out);
}